// round 9
// baseline (speedup 1.0000x reference)
#include <cuda_runtime.h>
#include <cuda_bf16.h>
#include <math.h>

#define NB   2
#define CIN  200
#define CQ   50
#define LL   16384
#define NSC  4
#define WIN  64
#define KCL  256
#define NCHUNK 8
#define CHSZ 2048

typedef unsigned long long ull;

#define FMA2(acc, a, b) asm("fma.rn.f32x2 %0, %1, %2, %0;" : "+l"(acc) : "l"(a), "l"(b))
#define CP_COMMIT() asm volatile("cp.async.commit_group;")
#define CP_WAIT1()  asm volatile("cp.async.wait_group 1;")
#define CP_WAIT0()  asm volatile("cp.async.wait_group 0;")

__device__ __forceinline__ ull dup2f(float x) {
    ull r; asm("mov.b64 %0, {%1, %1};" : "=l"(r) : "f"(x)); return r;
}
__device__ __forceinline__ float2 upk2(ull v) {
    float2 f; asm("mov.b64 {%0, %1}, %2;" : "=f"(f.x), "=f"(f.y) : "l"(v)); return f;
}
__device__ __forceinline__ ull ldp(const float* p) {
    return *reinterpret_cast<const ull*>(p);
}
__device__ __forceinline__ ull pk2(float x, float y) {
    ull r; asm("mov.b64 %0, {%1, %2};" : "=l"(r) : "f"(x), "f"(y)); return r;
}
__device__ __forceinline__ void ldq(const float* p, ull& a, ull& b) {
    float4 v = *reinterpret_cast<const float4*>(p);
    a = pk2(v.x, v.y); b = pk2(v.z, v.w);
}
__device__ __forceinline__ float4 q2(ull a, ull b) {
    float2 x = upk2(a), y = upk2(b);
    return make_float4(x.x, x.y, y.x, y.y);
}
__device__ __forceinline__ unsigned s2u(const void* p) {
    unsigned a;
    asm("{ .reg .u64 t; cvta.to.shared.u64 t, %1; cvt.u32.u64 %0, t; }" : "=r"(a) : "l"(p));
    return a;
}
__device__ __forceinline__ void cpa16(unsigned dst, const void* src) {
    asm volatile("cp.async.cg.shared.global [%0], [%1], 16;" :: "r"(dst), "l"(src));
}

// ---------------- device scratch ----------------
__device__ float g_xembed[(size_t)NB*LL*CQ];        // [n][l][c]
__device__ float g_yembed[(size_t)NB*LL*CIN];       // [n][l][o]
__device__ float g_att[(size_t)NB*NSC*LL*CIN];      // [n][u][l][oc]
__device__ int   g_perm[NB*NSC*LL];
__device__ float g_WyT[CIN*CIN];                    // [c][o]
__device__ float g_WoutT[(CIN*NSC)*CIN];            // [k][co]
__device__ float g_WxT[CIN*9*64];                   // [c][tap][o(64, zero-pad)]

// ---------------- prep (weight transposes) + counting sort, fused ----------------
__global__ void sortprep_kernel(const int* __restrict__ sem,
                                const float* __restrict__ Wx,
                                const float* __restrict__ Wy,
                                const float* __restrict__ Wout) {
    int u = blockIdx.x, n = blockIdx.y;
    int b = n*NSC + u;
    int tid = threadIdx.x;

    for (int i = b*256 + tid; i < CIN*CIN*NSC; i += NSC*NB*256) {
        if (i < CIN*CIN) {
            int o = i / CIN, c = i % CIN;
            g_WyT[c*CIN + o] = Wy[i];
        }
        {
            int co = i / (CIN*NSC), kk = i % (CIN*NSC);
            g_WoutT[(size_t)kk*CIN + co] = Wout[i];
        }
        if (i < CIN*9*64) {
            int c = i / 576, r = i % 576;
            int tap = r >> 6, o = r & 63;
            g_WxT[i] = (o < CQ) ? Wx[((size_t)o*CIN + c)*9 + tap] : 0.f;
        }
    }

    __shared__ int cnt[NCHUNK][32];
    __shared__ int start[NCHUNK][32];
    __shared__ int buf[NCHUNK][128];
    int w = tid >> 5, lane = tid & 31;
    cnt[w][lane] = 0;
    __syncthreads();
    const int* lab = sem + (size_t)b*LL + w*CHSZ;
    for (int i = lane; i < CHSZ; i += 32) atomicAdd(&cnt[w][lab[i] & 31], 1);
    __syncthreads();
    if (tid < 32) {
        int tot = 0;
        #pragma unroll
        for (int ch = 0; ch < NCHUNK; ch++) tot += cnt[ch][tid];
        int inc = tot;
        #pragma unroll
        for (int off = 1; off < 32; off <<= 1) {
            int v = __shfl_up_sync(0xffffffffu, inc, off);
            if (tid >= off) inc += v;
        }
        int run = inc - tot;
        #pragma unroll
        for (int ch = 0; ch < NCHUNK; ch++) { start[ch][tid] = run; run += cnt[ch][tid]; }
    }
    __syncthreads();
    int off = start[w][lane];
    int* pout = g_perm + b*LL;
    for (int t0 = 0; t0 < CHSZ; t0 += 128) {
        #pragma unroll
        for (int j = 0; j < 4; j++) buf[w][lane*4 + j] = lab[t0 + lane*4 + j];
        __syncwarp();
        #pragma unroll 8
        for (int e = 0; e < 128; e++) {
            if (buf[w][e] == lane) { pout[off] = w*CHSZ + t0 + e; off++; }
        }
        __syncwarp();
    }
}

// ---------------- conv3x3 reflect, 200->50, double-buffered, FFMA2 ----------------
__global__ __launch_bounds__(256) void conv_kernel(const float* __restrict__ input) {
    int tile = blockIdx.x, n = blockIdx.y;
    int l0 = tile * 64;
    int y = l0 >> 7, x0 = l0 & 127;
    __shared__ float inS[2][3*66];
    __shared__ float WxS[2][576];
    int tid = threadIdx.x, tx = tid & 15, ty = tid >> 4;
    ull acc2[4][2] = {{0ull,0ull},{0ull,0ull},{0ull,0ull},{0ull,0ull}};
    const float* inb = input + (size_t)n * CIN * LL;

    int in_off = -1;
    if (tid < 198) {
        int rr = tid / 66, cc = tid % 66;
        int gy = y - 1 + rr; gy = gy < 0 ? 1 : (gy > 127 ? 126 : gy);
        int gx = x0 - 1 + cc; gx = gx < 0 ? 1 : (gx > 127 ? 126 : gx);
        in_off = (gy << 7) + gx;
    }

    float wreg[3]; float ireg = 0.f;
    #pragma unroll
    for (int r = 0; r < 3; r++) { int e = tid + 256*r; if (e < 576) wreg[r] = g_WxT[e]; }
    if (in_off >= 0) ireg = inb[in_off];
    #pragma unroll
    for (int r = 0; r < 3; r++) { int e = tid + 256*r; if (e < 576) WxS[0][e] = wreg[r]; }
    if (in_off >= 0) inS[0][tid] = ireg;
    __syncthreads();

    for (int c = 0; c < CIN; ++c) {
        int p = c & 1;
        if (c + 1 < CIN) {
            #pragma unroll
            for (int r = 0; r < 3; r++) { int e = tid + 256*r; if (e < 576) wreg[r] = g_WxT[(c+1)*576 + e]; }
            if (in_off >= 0) ireg = inb[(size_t)(c+1)*LL + in_off];
        }
        const float* W = WxS[p];
        const float* I = inS[p];
        #pragma unroll
        for (int ky = 0; ky < 3; ky++)
        #pragma unroll
        for (int kx = 0; kx < 3; kx++) {
            ull w0, w1; ldq(&W[(ky*3 + kx)*64 + 4*tx], w0, w1);
            #pragma unroll
            for (int a = 0; a < 4; a++) {
                ull iv = dup2f(I[ky*66 + ty + 16*a + kx]);
                FMA2(acc2[a][0], iv, w0);
                FMA2(acc2[a][1], iv, w1);
            }
        }
        if (c + 1 < CIN) {
            #pragma unroll
            for (int r = 0; r < 3; r++) { int e = tid + 256*r; if (e < 576) WxS[p^1][e] = wreg[r]; }
            if (in_off >= 0) inS[p^1][tid] = ireg;
        }
        __syncthreads();
    }
    #pragma unroll
    for (int a = 0; a < 4; a++) {
        int l = l0 + ty + 16*a;
        size_t base = ((size_t)n*LL + l)*CQ + 4*tx;
        if (4*tx + 1 < CQ)
            *reinterpret_cast<float2*>(&g_xembed[base]) = upk2(acc2[a][0]);
        if (4*tx + 3 < CQ)
            *reinterpret_cast<float2*>(&g_xembed[base + 2]) = upk2(acc2[a][1]);
    }
}

// ---------------- 1x1 Wy GEMM, wide loads, FFMA2 ----------------
__global__ __launch_bounds__(256) void yembed_kernel(const float* __restrict__ input) {
    int tile = blockIdx.x, n = blockIdx.y;
    int l0 = tile * 64;
    __shared__ float inS[64*18];
    __shared__ float WyS[16*208];
    int tid = threadIdx.x, tx = tid & 31, ty8 = tid >> 5;
    ull acc2[13][2];
    #pragma unroll
    for (int pa = 0; pa < 13; pa++) { acc2[pa][0] = 0ull; acc2[pa][1] = 0ull; }
    const float* inb = input + (size_t)n * CIN * LL;
    for (int cb = 0; cb < 208; cb += 16) {
        __syncthreads();
        for (int e = tid; e < 16*64; e += 256) {
            int cc = e >> 6, li = e & 63;
            inS[li*18 + cc] = (cb + cc < CIN) ? inb[(size_t)(cb + cc)*LL + l0 + li] : 0.f;
        }
        for (int e = tid; e < 16*208; e += 256) {
            int cc = e / 208, o = e % 208;
            WyS[e] = (o < CIN && cb + cc < CIN) ? g_WyT[(cb + cc)*CIN + o] : 0.f;
        }
        __syncthreads();
        #pragma unroll
        for (int c2 = 0; c2 < 8; c2++) {
            float2 i0 = upk2(ldp(&inS[tx*18 + 2*c2]));
            float2 i1 = upk2(ldp(&inS[(tx + 32)*18 + 2*c2]));
            #pragma unroll
            for (int h = 0; h < 2; h++) {
                int cc = 2*c2 + h;
                ull d0 = dup2f(h ? i0.y : i0.x);
                ull d1 = dup2f(h ? i1.y : i1.x);
                #pragma unroll
                for (int q = 0; q < 6; q++) {
                    ull w0, w1; ldq(&WyS[cc*208 + 4*ty8 + 32*q], w0, w1);
                    FMA2(acc2[2*q][0], d0, w0);   FMA2(acc2[2*q][1], d1, w0);
                    FMA2(acc2[2*q+1][0], d0, w1); FMA2(acc2[2*q+1][1], d1, w1);
                }
                ull wt = ldp(&WyS[cc*208 + 192 + 2*ty8]);
                FMA2(acc2[12][0], d0, wt); FMA2(acc2[12][1], d1, wt);
            }
        }
    }
    float* yb0 = &g_yembed[((size_t)n*LL + l0 + tx)*CIN];
    float* yb1 = &g_yembed[((size_t)n*LL + l0 + tx + 32)*CIN];
    #pragma unroll
    for (int q = 0; q < 6; q++) {
        int o = 4*ty8 + 32*q;
        *reinterpret_cast<float4*>(&yb0[o]) = q2(acc2[2*q][0], acc2[2*q+1][0]);
        *reinterpret_cast<float4*>(&yb1[o]) = q2(acc2[2*q][1], acc2[2*q+1][1]);
    }
    if (ty8 < 4) {
        int o = 192 + 2*ty8;
        *reinterpret_cast<float2*>(&yb0[o]) = upk2(acc2[12][0]);
        *reinterpret_cast<float2*>(&yb1[o]) = upk2(acc2[12][1]);
    }
}

// ---------------- attention: 32-lane-distinct LDS tiling (unchanged from R8) ----------------
__global__ __launch_bounds__(256, 2) void attn_kernel() {
    extern __shared__ float sm[];
    float* P   = sm;                  // 12544 fl
    float* Vs  = sm + 64*196;         // 2 x 6656 fl
    float* KsT = Vs;                  // 9800 fl
    float* Qs  = KsT + 50*196;        // 3328 fl
    __shared__ int lperm[192];
    int k = blockIdx.x, u = blockIdx.y, n = blockIdx.z;
    int tid = threadIdx.x;
    int lane = tid & 31, w = tid >> 5;
    int rbase = 8*w;

    const int* pbase = g_perm + (n*NSC + u)*LL;
    if (tid < 192) {
        int jj = tid & 63;
        int kk = tid < 64 ? k : (tid < 128 ? (k + KCL - 1) & (KCL - 1) : (k + 1) & (KCL - 1));
        lperm[tid] = pbase[kk*WIN + jj];
    }
    __syncthreads();

    const float* xb = g_xembed + (size_t)n*LL*CQ;
    for (int e = tid; e < 192*CQ; e += 256) {
        int j = e / CQ, c = e - j*CQ;
        KsT[c*196 + j] = xb[(size_t)lperm[j]*CQ + c];
    }
    for (int e = tid; e < 64*25; e += 256) {
        int i = e / 25, c2 = e - i*25;
        *reinterpret_cast<float2*>(&Qs[i*52 + 2*c2]) =
            *reinterpret_cast<const float2*>(&xb[(size_t)lperm[i]*CQ + 2*c2]);
    }
    __syncthreads();
    if (tid < 192) {
        float ss = 0.f;
        #pragma unroll 10
        for (int c = 0; c < CQ; c++) { float v = KsT[c*196 + tid]; ss += v*v; }
        float s = 1.f / fmaxf(sqrtf(ss), 5e-5f);
        #pragma unroll 10
        for (int c = 0; c < CQ; c++) KsT[c*196 + tid] *= s;
    }
    __syncthreads();

    // S = Q @ K^T
    {
        int jc0 = 4*lane;
        int jc1 = 128 + 4*(lane & 15);
        ull accS[8][4];
        #pragma unroll
        for (int i = 0; i < 8; i++)
            #pragma unroll
            for (int t = 0; t < 4; t++) accS[i][t] = 0ull;
        #pragma unroll 2
        for (int c = 0; c < CQ; c++) {
            ull k0a, k0b, k1a, k1b;
            ldq(&KsT[c*196 + jc0], k0a, k0b);
            ldq(&KsT[c*196 + jc1], k1a, k1b);
            #pragma unroll
            for (int i = 0; i < 8; i++) {
                ull qd = dup2f(Qs[(rbase + i)*52 + c]);
                FMA2(accS[i][0], qd, k0a); FMA2(accS[i][1], qd, k0b);
                FMA2(accS[i][2], qd, k1a); FMA2(accS[i][3], qd, k1b);
            }
        }
        #pragma unroll
        for (int i = 0; i < 8; i++) {
            int r = rbase + i;
            *reinterpret_cast<float4*>(&P[r*196 + jc0]) = q2(accS[i][0], accS[i][1]);
            if (lane < 16)
                *reinterpret_cast<float4*>(&P[r*196 + jc1]) = q2(accS[i][2], accS[i][3]);
        }
    }
    __syncthreads();

    const float* yb = g_yembed + (size_t)n*LL*CIN;
    #pragma unroll
    for (int c0i = 0; c0i < 2; c0i++) {
        unsigned vb = s2u(Vs + c0i*6656);
        for (int e = tid; e < 32*50; e += 256) {
            int row = e / 50, qd = e - row*50;
            cpa16(vb + (row*208 + 4*qd)*4,
                  yb + (size_t)lperm[c0i*32 + row]*CIN + 4*qd);
        }
        CP_COMMIT();
    }
    // softmax over 192 cols
    {
        int r = tid >> 2, q = tid & 3;
        float* prow = P + r*196 + q*48;
        float mx = -1e30f;
        #pragma unroll 8
        for (int m = 0; m < 48; m++) mx = fmaxf(mx, prow[m]);
        mx = fmaxf(mx, __shfl_xor_sync(0xffffffffu, mx, 1));
        mx = fmaxf(mx, __shfl_xor_sync(0xffffffffu, mx, 2));
        float sum = 0.f;
        #pragma unroll 8
        for (int m = 0; m < 48; m++) { float e = __expf(prow[m] - mx); prow[m] = e; sum += e; }
        sum += __shfl_xor_sync(0xffffffffu, sum, 1);
        sum += __shfl_xor_sync(0xffffffffu, sum, 2);
        float inv = 1.f / sum;
        #pragma unroll 8
        for (int m = 0; m < 48; m++) prow[m] *= inv;
    }

    // O = P @ V
    int c0 = 4*lane;
    int c1 = 128 + 4*(lane < 18 ? lane : 0);
    ull accO[8][4];
    #pragma unroll
    for (int i = 0; i < 8; i++)
        #pragma unroll
        for (int t = 0; t < 4; t++) accO[i][t] = 0ull;
    for (int ch = 0; ch < 6; ch++) {
        if (ch < 5) CP_WAIT1(); else CP_WAIT0();
        __syncthreads();
        const float* V = Vs + (ch & 1)*6656;
        #pragma unroll 2
        for (int jj = 0; jj < 32; jj++) {
            int j = ch*32 + jj;
            ull v0a, v0b, v1a, v1b;
            ldq(&V[jj*208 + c0], v0a, v0b);
            ldq(&V[jj*208 + c1], v1a, v1b);
            #pragma unroll
            for (int i = 0; i < 8; i++) {
                ull pd = dup2f(P[(rbase + i)*196 + j]);
                FMA2(accO[i][0], pd, v0a); FMA2(accO[i][1], pd, v0b);
                FMA2(accO[i][2], pd, v1a); FMA2(accO[i][3], pd, v1b);
            }
        }
        __syncthreads();
        if (ch + 2 < 6) {
            unsigned vb = s2u(Vs + (ch & 1)*6656);
            for (int e = tid; e < 32*50; e += 256) {
                int row = e / 50, qd = e - row*50;
                cpa16(vb + (row*208 + 4*qd)*4,
                      yb + (size_t)lperm[(ch + 2)*32 + row]*CIN + 4*qd);
            }
            CP_COMMIT();
        }
    }
    float* ob = g_att + (size_t)(n*NSC + u)*LL*CIN;
    #pragma unroll
    for (int i = 0; i < 8; i++) {
        float* o = ob + (size_t)lperm[rbase + i]*CIN;
        *reinterpret_cast<float4*>(&o[c0]) = q2(accO[i][0], accO[i][1]);
        if (lane < 18)
            *reinterpret_cast<float4*>(&o[c1]) = q2(accO[i][2], accO[i][3]);
    }
}

// ---------------- Wout 1x1 (K=800): lane-distinct W, broadcast att, smem-transposed epilogue ----
// dyn smem: attB 2 x [64][36] | WoB 2 x [32][208]; epilogue reuses osm as Tr[64][224]
__global__ __launch_bounds__(256, 2) void out_kernel(const float* __restrict__ input,
                                                     const float* __restrict__ bout,
                                                     float* __restrict__ out) {
    extern __shared__ float osm[];
    float* attB = osm;                 // 2 x 2304 fl
    float* WoB  = osm + 2*2304;        // 2 x 6656 fl
    int tile = blockIdx.x, n = blockIdx.y;
    int l0 = tile * 64;
    int tid = threadIdx.x;
    int lane = tid & 31, w = tid >> 5;
    int rbase = 8*w;
    int c0 = 4*lane;
    int c1 = 128 + 4*(lane < 18 ? lane : 0);

    ull acc[8][4];
    #pragma unroll
    for (int i = 0; i < 8; i++)
        #pragma unroll
        for (int t = 0; t < 4; t++) acc[i][t] = 0ull;

    auto issue = [&](int c, int bfr) {
        int k0 = c*32;
        unsigned ab = s2u(attB + bfr*2304);
        for (int e = tid; e < 512; e += 256) {
            int li = e >> 3, qd = e & 7;
            int kc = 4*qd, kk = k0 + kc;
            int u = kk / CIN, oc = kk - u*CIN;
            cpa16(ab + (li*36 + kc)*4,
                  g_att + ((size_t)(n*NSC + u)*LL + l0 + li)*CIN + oc);
        }
        unsigned wb = s2u(WoB + bfr*6656);
        for (int e = tid; e < 1600; e += 256) {
            int kc = e / 50, qd = e - kc*50;
            cpa16(wb + (kc*208 + 4*qd)*4,
                  g_WoutT + (size_t)(k0 + kc)*CIN + 4*qd);
        }
        CP_COMMIT();
    };

    issue(0, 0);
    issue(1, 1);
    for (int c = 0; c < 25; c++) {
        if (c < 24) CP_WAIT1(); else CP_WAIT0();
        __syncthreads();
        const float* aS = attB + (c & 1)*2304;
        const float* wS = WoB + (c & 1)*6656;
        #pragma unroll 4
        for (int kc = 0; kc < 32; kc++) {
            ull w0a, w0b, w1a, w1b;
            ldq(&wS[kc*208 + c0], w0a, w0b);
            ldq(&wS[kc*208 + c1], w1a, w1b);
            #pragma unroll
            for (int i = 0; i < 8; i++) {
                ull ad = dup2f(aS[(rbase + i)*36 + kc]);
                FMA2(acc[i][0], ad, w0a); FMA2(acc[i][1], ad, w0b);
                FMA2(acc[i][2], ad, w1a); FMA2(acc[i][3], ad, w1b);
            }
        }
        __syncthreads();
        if (c + 2 < 25) issue(c + 2, c & 1);
    }

    // epilogue: transpose via smem (stride 224, quad XOR swizzle), coalesced stores
    __syncthreads();
    float* Tr = osm;   // 64 x 224 floats = 57344 B
    #pragma unroll
    for (int i = 0; i < 8; i++) {
        int l = rbase + i;
        int sg = (l >> 2) & 7;
        int q0p = lane ^ sg;
        *reinterpret_cast<float4*>(&Tr[l*224 + 4*q0p]) = q2(acc[i][0], acc[i][1]);
        if (lane < 18) {
            int q1p = (32 + lane) ^ sg;
            *reinterpret_cast<float4*>(&Tr[l*224 + 4*q1p]) = q2(acc[i][2], acc[i][3]);
        }
    }
    __syncthreads();
    for (int e = tid; e < CIN*16; e += 256) {
        int co = e >> 4, lq = e & 15;
        int q = co >> 2, cr = co & 3;
        int sg = lq & 7;
        int wbase = 4*lq*224 + 4*(q ^ sg) + cr;
        float4 v;
        v.x = Tr[wbase];
        v.y = Tr[wbase + 224];
        v.z = Tr[wbase + 448];
        v.w = Tr[wbase + 672];
        size_t i0 = ((size_t)n*CIN + co)*LL + l0 + 4*lq;
        float4 inp = *reinterpret_cast<const float4*>(&input[i0]);
        float bo = bout[co];
        v.x += bo + inp.x; v.y += bo + inp.y; v.z += bo + inp.z; v.w += bo + inp.w;
        *reinterpret_cast<float4*>(&out[i0]) = v;
    }
}

// ---------------- launch ----------------
extern "C" void kernel_launch(void* const* d_in, const int* in_sizes, int n_in,
                              void* d_out, int out_size) {
    const float* input = (const float*)d_in[0];
    const int*   sem   = (const int*)d_in[1];
    const float* Wx    = (const float*)d_in[2];
    const float* Wy    = (const float*)d_in[3];
    const float* Wout  = (const float*)d_in[4];
    const float* bout  = (const float*)d_in[5];
    float* out = (float*)d_out;

    cudaFuncSetAttribute(attn_kernel, cudaFuncAttributeMaxDynamicSharedMemorySize, 103424);
    cudaFuncSetAttribute(out_kernel,  cudaFuncAttributeMaxDynamicSharedMemorySize, 71680);

    sortprep_kernel<<<dim3(NSC, NB), 256>>>(sem, Wx, Wy, Wout);
    conv_kernel<<<dim3(LL/64, NB), 256>>>(input);
    yembed_kernel<<<dim3(LL/64, NB), 256>>>(input);
    attn_kernel<<<dim3(KCL, NSC, NB), 256, 103424>>>();
    out_kernel<<<dim3(LL/64, NB), 256, 71680>>>(input, bout, out);
}